// round 8
// baseline (speedup 1.0000x reference)
#include <cuda_runtime.h>
#include <cuda_fp16.h>
#include <cstdint>

// SimpleDistanceLoss:
//   search: S[m][n] = bsq[n] - 2<a_m,b_n> via fp16 m16n8k16 mma.sync, fp16
//           accumulators (fastest legacy-pipe format on sm_103a, rt~12.6).
//           bsq folded into the C operand of the first k-step. Search tracks
//           the winning candidate GROUP (tile, col-half, lane-pair, parity).
//   tail:   exact fp32 recompute over the 8 candidate columns of each row's
//           winning group (split across thread pairs), fused block sums and
//           fused final reduction (threadfence-reduction pattern).

#define NPTS   16384
#define DDIM   64
#define NTILES 128
#define NBLK   128

__device__ uint4 g_aunits[NBLK * 1024];    // fragment-unit layout of -2*A (fp16)
__device__ uint4 g_bunits[NTILES * 1024];  // fragment-unit layout of B (fp16)
__device__ __align__(16) __half g_bsqh[NPTS];  // fp16 ||b||^2
__device__ float g_bsum[NBLK];
__device__ int g_done;

// ---- smem byte offsets ----
#define SM_A     0
#define SM_B0    16384
#define SM_B1    32768
#define SM_BSQ0  49152                     // 256 B (128 halfs)
#define SM_BSQ1  49408
#define SM_REDV  49664                     // float[128][2]
#define SM_REDM  50688                     // int[128][2]
#define SM_WS    51712                     // float[8]
#define SMEM_BYTES 51744

static __device__ __forceinline__ uint32_t smem_u32(const void* p) {
    uint32_t a;
    asm("{ .reg .u64 t; cvta.to.shared.u64 t, %1; cvt.u32.u64 %0, t; }" : "=r"(a) : "l"(p));
    return a;
}
#define CP16(sm, gp) \
    asm volatile("cp.async.cg.shared.global [%0], [%1], 16;" :: "r"(sm), "l"(gp))
#define CP_COMMIT() asm volatile("cp.async.commit_group;" ::: "memory")
#define CP_WAIT0()  asm volatile("cp.async.wait_group 0;" ::: "memory")

// fp16-accumulator MMA: D,C are 2 b32 regs (f16x2).
static __device__ __forceinline__ void mma_h_acc(uint32_t c[2], uint32_t a0, uint32_t a1,
                                                 uint32_t a2, uint32_t a3,
                                                 uint32_t b0, uint32_t b1) {
    asm("mma.sync.aligned.m16n8k16.row.col.f16.f16.f16.f16 "
        "{%0,%1},{%2,%3,%4,%5},{%6,%7},{%0,%1};"
        : "+r"(c[0]), "+r"(c[1])
        : "r"(a0), "r"(a1), "r"(a2), "r"(a3), "r"(b0), "r"(b1));
}
static __device__ __forceinline__ void mma_h_init(uint32_t c[2], uint32_t a0, uint32_t a1,
                                                  uint32_t a2, uint32_t a3,
                                                  uint32_t b0, uint32_t b1, uint32_t bq) {
    asm("mma.sync.aligned.m16n8k16.row.col.f16.f16.f16.f16 "
        "{%0,%1},{%2,%3,%4,%5},{%6,%7},{%8,%8};"
        : "=r"(c[0]), "=r"(c[1])
        : "r"(a0), "r"(a1), "r"(a2), "r"(a3), "r"(b0), "r"(b1), "r"(bq));
}

// ---------------------------------------------------------------------------
// Prep (grid 512): blocks 0..255 -> A half-tiles, 256..511 -> B half-tiles.
// Each block converts 64 rows (fp32 -> fp16, A scaled by -2), computes norms,
// and repacks into the m16n8k16 fragment-unit layout:
// Unit (ks, blk, s): 8 halfs {X[x][k],X[x][k+1], X[x+8][k],X[x+8][k+1],
//                             X[x][k+8],X[x][k+9], X[x+8][k+8],X[x+8][k+9]}
// with x = blk*16 + (s>>2), k = ks*16 + (s&3)*2.
// ---------------------------------------------------------------------------
__global__ __launch_bounds__(256)
void prep_kernel(const float* __restrict__ A, const float* __restrict__ B) {
    __shared__ __half sh[64 * 64];
    const int tid = threadIdx.x;
    const int b = blockIdx.x;
    if (b == 0 && tid == 0) g_done = 0;

    const bool isB = b >= 256;
    const int t2 = b & 255;
    const int tile = t2 >> 1, h = t2 & 1;       // half-tile: rows h*64..h*64+63
    const float sc = isB ? 1.0f : -2.0f;

    const int r = tid >> 2;                     // local row 0..63
    const int q = tid & 3;                      // quarter of the row (16 floats)
    const float4* s4 = reinterpret_cast<const float4*>(isB ? B : A) +
                       ((size_t)tile * 128 + h * 64 + r) * 16 + q * 4;
    float nrm = 0.f;
    half2* sh2 = reinterpret_cast<half2*>(sh);
#pragma unroll
    for (int i = 0; i < 4; i++) {
        float4 v = s4[i];
        nrm += v.x * v.x + v.y * v.y + v.z * v.z + v.w * v.w;
        sh2[r * 32 + q * 8 + i * 2 + 0] = __floats2half2_rn(sc * v.x, sc * v.y);
        sh2[r * 32 + q * 8 + i * 2 + 1] = __floats2half2_rn(sc * v.z, sc * v.w);
    }
    nrm += __shfl_xor_sync(0xffffffffu, nrm, 1);
    nrm += __shfl_xor_sync(0xffffffffu, nrm, 2);
    __syncthreads();
    if (isB && q == 0) g_bsqh[tile * 128 + h * 64 + r] = __float2half_rn(nrm);

    uint4* dst = (isB ? g_bunits : g_aunits) + (size_t)tile * 1024;
#pragma unroll
    for (int i = 0; i < 2; i++) {
        int lu = tid + i * 256;                 // 512 local units
        int ks = lu >> 7, blkl = (lu >> 5) & 3, s = lu & 31;
        int blk = h * 4 + blkl;
        int xl = blkl * 16 + (s >> 2), k = ks * 16 + (s & 3) * 2;
        const uint32_t* p0 = reinterpret_cast<const uint32_t*>(&sh[xl * 64 + k]);
        const uint32_t* p1 = reinterpret_cast<const uint32_t*>(&sh[(xl + 8) * 64 + k]);
        uint4 v;
        v.x = p0[0]; v.y = p1[0]; v.z = p0[4]; v.w = p1[4];
        dst[(ks * 8 + blk) * 32 + s] = v;
    }
}

// ---------------------------------------------------------------------------
// Main: 128 CTAs x 256 threads, 8 compute warps (warp tile 32x64).
// ---------------------------------------------------------------------------
__global__ __launch_bounds__(256, 1)
void dist_kernel(const float* __restrict__ A, const float* __restrict__ B,
                 float* __restrict__ out) {
    extern __shared__ char sm[];
    const uint32_t smb = smem_u32(sm);
    const int tid = threadIdx.x;
    const int wid = tid >> 5, lane = tid & 31;
    const int wm = wid & 3, wn = wid >> 2;     // rows wm*32, cols wn*64
    const int rowbase = blockIdx.x * 128;
    const int idxbase = wn * 64 + (lane & 3) * 2;

    // ---- prologue: A units + B tile 0 + bsq tile 0 ----
    {
        const uint4* gA = g_aunits + (size_t)blockIdx.x * 1024;
        const uint4* gB = g_bunits;
#pragma unroll
        for (int i = 0; i < 4; i++) {
            int u = tid + i * 256;
            CP16(smb + SM_A + u * 16, gA + u);
            CP16(smb + SM_B0 + u * 16, gB + u);
        }
        if (tid < 16) CP16(smb + SM_BSQ0 + tid * 16, reinterpret_cast<const uint4*>(g_bsqh) + tid);
        CP_COMMIT();
        CP_WAIT0();
        __syncthreads();
    }

    const uint4* Au = reinterpret_cast<const uint4*>(sm + SM_A);
    float pmin[8];
    int ptile[8];
#pragma unroll
    for (int s = 0; s < 8; s++) { pmin[s] = 3.4e38f; ptile[s] = 0; }

    for (int t = 0; t < NTILES; t++) {
        if (t + 1 < NTILES) {
            const uint4* gB = g_bunits + (size_t)(t + 1) * 1024;
            const uint32_t dstB = smb + ((t & 1) ? SM_B0 : SM_B1);
#pragma unroll
            for (int i = 0; i < 4; i++) {
                int u = tid + i * 256;
                CP16(dstB + u * 16, gB + u);
            }
            if (tid < 16)
                CP16(smb + ((t & 1) ? SM_BSQ0 : SM_BSQ1) + tid * 16,
                     reinterpret_cast<const uint4*>(g_bsqh + (t + 1) * 128) + tid);
            CP_COMMIT();
        }

        const uint4* Bu = reinterpret_cast<const uint4*>(sm + ((t & 1) ? SM_B1 : SM_B0));
        const char* bsqs = sm + ((t & 1) ? SM_BSQ1 : SM_BSQ0);

        uint32_t bq[8];
#pragma unroll
        for (int j = 0; j < 8; j++)
            bq[j] = *reinterpret_cast<const uint32_t*>(
                bsqs + (idxbase + (j >> 1) * 16 + (j & 1) * 8) * 2);

        uint32_t acc[2][8][2];
#pragma unroll
        for (int ks = 0; ks < 4; ks++) {
            uint4 af[2], bf[4];
#pragma unroll
            for (int mt = 0; mt < 2; mt++)
                af[mt] = Au[(ks * 8 + wm * 2 + mt) * 32 + lane];
#pragma unroll
            for (int p = 0; p < 4; p++)
                bf[p] = Bu[(ks * 8 + wn * 4 + p) * 32 + lane];
#pragma unroll
            for (int mt = 0; mt < 2; mt++)
#pragma unroll
                for (int p = 0; p < 4; p++) {
                    if (ks == 0) {
                        mma_h_init(acc[mt][2 * p],     af[mt].x, af[mt].y, af[mt].z, af[mt].w,
                                   bf[p].x, bf[p].z, bq[2 * p]);
                        mma_h_init(acc[mt][2 * p + 1], af[mt].x, af[mt].y, af[mt].z, af[mt].w,
                                   bf[p].y, bf[p].w, bq[2 * p + 1]);
                    } else {
                        mma_h_acc(acc[mt][2 * p],     af[mt].x, af[mt].y, af[mt].z, af[mt].w,
                                  bf[p].x, bf[p].z);
                        mma_h_acc(acc[mt][2 * p + 1], af[mt].x, af[mt].y, af[mt].z, af[mt].w,
                                  bf[p].y, bf[p].w);
                    }
                }
        }

        // fold tile minimum per (mt, row-half) slot across the 8 j-blocks
#pragma unroll
        for (int mt = 0; mt < 2; mt++)
#pragma unroll
            for (int rh = 0; rh < 2; rh++) {
                __half2 mn = *reinterpret_cast<__half2*>(&acc[mt][0][rh]);
#pragma unroll
                for (int j = 1; j < 8; j++)
                    mn = __hmin2(mn, *reinterpret_cast<__half2*>(&acc[mt][j][rh]));
                float2 f = __half22float2(mn);
                const int s = mt * 2 + rh;
                if (f.x < pmin[2 * s + 0]) { pmin[2 * s + 0] = f.x; ptile[2 * s + 0] = t; }
                if (f.y < pmin[2 * s + 1]) { pmin[2 * s + 1] = f.y; ptile[2 * s + 1] = t; }
            }

        CP_WAIT0();
        __syncthreads();
    }

    // ---- per-row winner (group) across parity, lanes, wn-halves ----
    float* redv = reinterpret_cast<float*>(sm + SM_REDV);
    int*   redm = reinterpret_cast<int*>(sm + SM_REDM);
#pragma unroll
    for (int s = 0; s < 4; s++) {
        float v0 = pmin[2 * s], v1 = pmin[2 * s + 1];
        int h = (v1 < v0) ? 1 : 0;
        float v = h ? v1 : v0;
        int meta = (ptile[2 * s + h] << 4) | (wn << 3) | ((lane & 3) * 2 + h);
#pragma unroll
        for (int mk = 1; mk <= 2; mk <<= 1) {
            float ov = __shfl_xor_sync(0xffffffffu, v, mk);
            int om = __shfl_xor_sync(0xffffffffu, meta, mk);
            if (ov < v) { v = ov; meta = om; }
        }
        if ((lane & 3) == 0) {
            int row = wm * 32 + (s >> 1) * 16 + (s & 1) * 8 + (lane >> 2);
            redv[row * 2 + wn] = v;
            redm[row * 2 + wn] = meta;
        }
    }
    __syncthreads();

    // ---- exact fp32 recompute: thread PAIRS split the 8 candidate columns ----
    float* ws = reinterpret_cast<float*>(sm + SM_WS);
    {
        const int row = tid >> 1, par = tid & 1;
        float v0 = redv[row * 2 + 0], v1 = redv[row * 2 + 1];
        int sel = (v1 < v0) ? 1 : 0;
        int meta = redm[row * 2 + sel];
        int base = (meta >> 4) * 128 + ((meta >> 3) & 1) * 64 + (meta & 7);

        const float4* ar = reinterpret_cast<const float4*>(A) + (size_t)(rowbase + row) * 16;
        float4 a4[16];
#pragma unroll
        for (int i = 0; i < 16; i++) a4[i] = ar[i];

        float best = 3.4e38f;
#pragma unroll
        for (int jj = 0; jj < 4; jj++) {
            int col = base + (2 * jj + par) * 8;
            const float4* br = reinterpret_cast<const float4*>(B) + (size_t)col * 16;
            float s = 0.f;
#pragma unroll
            for (int i = 0; i < 16; i++) {
                float4 b4 = br[i];
                float dx = a4[i].x - b4.x, dy = a4[i].y - b4.y;
                float dz = a4[i].z - b4.z, dw = a4[i].w - b4.w;
                s += dx * dx + dy * dy + dz * dz + dw * dw;
            }
            best = fminf(best, s);
        }
        best = fminf(best, __shfl_xor_sync(0xffffffffu, best, 1));
        // warp sum counts each row twice -> halve (exact)
#pragma unroll
        for (int mk = 16; mk; mk >>= 1) best += __shfl_xor_sync(0xffffffffu, best, mk);
        if (lane == 0) ws[wid] = best * 0.5f;
    }
    __syncthreads();
    if (tid == 0) {
        float t = 0.f;
#pragma unroll
        for (int i = 0; i < 8; i++) t += ws[i];
        g_bsum[blockIdx.x] = t;
    }

    // ---- fused final reduction: last CTA sums all 128 partials ----
    __shared__ int s_last;
    __threadfence();
    if (tid == 0) s_last = (atomicAdd(&g_done, 1) == NBLK - 1) ? 1 : 0;
    __syncthreads();
    if (s_last && tid < 32) {
        __threadfence();
        float v = __ldcg(&g_bsum[tid]) + __ldcg(&g_bsum[tid + 32]) +
                  __ldcg(&g_bsum[tid + 64]) + __ldcg(&g_bsum[tid + 96]);
#pragma unroll
        for (int mk = 16; mk; mk >>= 1) v += __shfl_xor_sync(0xffffffffu, v, mk);
        if (tid == 0) out[0] = v;
    }
}

extern "C" void kernel_launch(void* const* d_in, const int* in_sizes, int n_in,
                              void* d_out, int out_size) {
    const float* A = (const float*)d_in[0];
    const float* B = (const float*)d_in[1];
    float* out = (float*)d_out;

    cudaFuncSetAttribute(dist_kernel, cudaFuncAttributeMaxDynamicSharedMemorySize, SMEM_BYTES);

    prep_kernel<<<512, 256>>>(A, B);
    dist_kernel<<<NBLK, 256, SMEM_BYTES>>>(A, B, out);
}

// round 9
// speedup vs baseline: 1.0035x; 1.0035x over previous
#include <cuda_runtime.h>
#include <cuda_fp16.h>
#include <cstdint>

// SimpleDistanceLoss:
//   search: S[m][n] = bsq[n] - 2<a_m,b_n> via fp16 m16n8k16 mma.sync, fp16
//           accumulators. bsq folded into the C operand of the first k-step.
//           512-thread CTAs, 16 warps, 32x32 warp tiles -> 4 warps/SMSP for
//           latency hiding (R8 ncu: tensor pipe only 42% busy at 8 warps).
//   tail:   exact fp32 recompute of the 4 candidate columns of each row's
//           winning group (1 col/thread, streamed), fused final reduction.

#define NPTS   16384
#define DDIM   64
#define NTILES 128
#define NBLK   128
#define NT     512

__device__ uint4 g_aunits[NBLK * 1024];    // fragment-unit layout of -2*A (fp16)
__device__ uint4 g_bunits[NTILES * 1024];  // fragment-unit layout of B (fp16)
__device__ __align__(16) __half g_bsqh[NPTS];
__device__ float g_bsum[NBLK];
__device__ int g_done;

// ---- smem byte offsets ----
#define SM_A     0
#define SM_B0    16384
#define SM_B1    32768
#define SM_BSQ0  49152                     // 256 B
#define SM_BSQ1  49408
#define SM_REDV  49664                     // float[128][4]
#define SM_REDM  51712                     // int[128][4]
#define SM_WS    53760                     // float[16]
#define SMEM_BYTES 53824

static __device__ __forceinline__ uint32_t smem_u32(const void* p) {
    uint32_t a;
    asm("{ .reg .u64 t; cvta.to.shared.u64 t, %1; cvt.u32.u64 %0, t; }" : "=r"(a) : "l"(p));
    return a;
}
#define CP16(sm, gp) \
    asm volatile("cp.async.cg.shared.global [%0], [%1], 16;" :: "r"(sm), "l"(gp))
#define CP_COMMIT() asm volatile("cp.async.commit_group;" ::: "memory")
#define CP_WAIT0()  asm volatile("cp.async.wait_group 0;" ::: "memory")

static __device__ __forceinline__ void mma_h_acc(uint32_t c[2], uint32_t a0, uint32_t a1,
                                                 uint32_t a2, uint32_t a3,
                                                 uint32_t b0, uint32_t b1) {
    asm("mma.sync.aligned.m16n8k16.row.col.f16.f16.f16.f16 "
        "{%0,%1},{%2,%3,%4,%5},{%6,%7},{%0,%1};"
        : "+r"(c[0]), "+r"(c[1])
        : "r"(a0), "r"(a1), "r"(a2), "r"(a3), "r"(b0), "r"(b1));
}
static __device__ __forceinline__ void mma_h_init(uint32_t c[2], uint32_t a0, uint32_t a1,
                                                  uint32_t a2, uint32_t a3,
                                                  uint32_t b0, uint32_t b1, uint32_t bq) {
    asm("mma.sync.aligned.m16n8k16.row.col.f16.f16.f16.f16 "
        "{%0,%1},{%2,%3,%4,%5},{%6,%7},{%8,%8};"
        : "=r"(c[0]), "=r"(c[1])
        : "r"(a0), "r"(a1), "r"(a2), "r"(a3), "r"(b0), "r"(b1), "r"(bq));
}

// ---------------------------------------------------------------------------
// Prep (grid 512): blocks 0..255 -> A half-tiles, 256..511 -> B half-tiles.
// Fragment unit (ks, blk, s): 8 halfs {X[x][k],X[x][k+1], X[x+8][k],X[x+8][k+1],
//   X[x][k+8],X[x][k+9], X[x+8][k+8],X[x+8][k+9]}, x = blk*16+(s>>2),
//   k = ks*16+(s&3)*2.
// ---------------------------------------------------------------------------
__global__ __launch_bounds__(256)
void prep_kernel(const float* __restrict__ A, const float* __restrict__ B) {
    __shared__ __half sh[64 * 64];
    const int tid = threadIdx.x;
    const int b = blockIdx.x;
    if (b == 0 && tid == 0) g_done = 0;

    const bool isB = b >= 256;
    const int t2 = b & 255;
    const int tile = t2 >> 1, h = t2 & 1;
    const float sc = isB ? 1.0f : -2.0f;

    const int r = tid >> 2;
    const int q = tid & 3;
    const float4* s4 = reinterpret_cast<const float4*>(isB ? B : A) +
                       ((size_t)tile * 128 + h * 64 + r) * 16 + q * 4;
    float nrm = 0.f;
    half2* sh2 = reinterpret_cast<half2*>(sh);
#pragma unroll
    for (int i = 0; i < 4; i++) {
        float4 v = s4[i];
        nrm += v.x * v.x + v.y * v.y + v.z * v.z + v.w * v.w;
        sh2[r * 32 + q * 8 + i * 2 + 0] = __floats2half2_rn(sc * v.x, sc * v.y);
        sh2[r * 32 + q * 8 + i * 2 + 1] = __floats2half2_rn(sc * v.z, sc * v.w);
    }
    nrm += __shfl_xor_sync(0xffffffffu, nrm, 1);
    nrm += __shfl_xor_sync(0xffffffffu, nrm, 2);
    __syncthreads();
    if (isB && q == 0) g_bsqh[tile * 128 + h * 64 + r] = __float2half_rn(nrm);

    uint4* dst = (isB ? g_bunits : g_aunits) + (size_t)tile * 1024;
#pragma unroll
    for (int i = 0; i < 2; i++) {
        int lu = tid + i * 256;
        int ks = lu >> 7, blkl = (lu >> 5) & 3, s = lu & 31;
        int blk = h * 4 + blkl;
        int xl = blkl * 16 + (s >> 2), k = ks * 16 + (s & 3) * 2;
        const uint32_t* p0 = reinterpret_cast<const uint32_t*>(&sh[xl * 64 + k]);
        const uint32_t* p1 = reinterpret_cast<const uint32_t*>(&sh[(xl + 8) * 64 + k]);
        uint4 v;
        v.x = p0[0]; v.y = p1[0]; v.z = p0[4]; v.w = p1[4];
        dst[(ks * 8 + blk) * 32 + s] = v;
    }
}

// ---------------------------------------------------------------------------
// Main: 128 CTAs x 512 threads, 16 compute warps, warp tile 32x32.
// ---------------------------------------------------------------------------
__global__ __launch_bounds__(NT, 1)
void dist_kernel(const float* __restrict__ A, const float* __restrict__ B,
                 float* __restrict__ out) {
    extern __shared__ char sm[];
    const uint32_t smb = smem_u32(sm);
    const int tid = threadIdx.x;
    const int wid = tid >> 5, lane = tid & 31;
    const int wm = wid & 3, wn = wid >> 2;     // rows wm*32, cols wn*32
    const int rowbase = blockIdx.x * 128;

    // ---- prologue: A units + B tile 0 + bsq tile 0 ----
    {
        const uint4* gA = g_aunits + (size_t)blockIdx.x * 1024;
        const uint4* gB = g_bunits;
#pragma unroll
        for (int i = 0; i < 2; i++) {
            int u = tid + i * NT;
            CP16(smb + SM_A + u * 16, gA + u);
            CP16(smb + SM_B0 + u * 16, gB + u);
        }
        if (tid < 16) CP16(smb + SM_BSQ0 + tid * 16, reinterpret_cast<const uint4*>(g_bsqh) + tid);
        CP_COMMIT();
        CP_WAIT0();
        __syncthreads();
    }

    const uint4* Au = reinterpret_cast<const uint4*>(sm + SM_A);
    float pmin[8];
    int ptile[8];
#pragma unroll
    for (int s = 0; s < 8; s++) { pmin[s] = 3.4e38f; ptile[s] = 0; }

    for (int t = 0; t < NTILES; t++) {
        if (t + 1 < NTILES) {
            const uint4* gB = g_bunits + (size_t)(t + 1) * 1024;
            const uint32_t dstB = smb + ((t & 1) ? SM_B0 : SM_B1);
#pragma unroll
            for (int i = 0; i < 2; i++) {
                int u = tid + i * NT;
                CP16(dstB + u * 16, gB + u);
            }
            if (tid < 16)
                CP16(smb + ((t & 1) ? SM_BSQ0 : SM_BSQ1) + tid * 16,
                     reinterpret_cast<const uint4*>(g_bsqh + (t + 1) * 128) + tid);
            CP_COMMIT();
        }

        const uint4* Bu = reinterpret_cast<const uint4*>(sm + ((t & 1) ? SM_B1 : SM_B0));
        const char* bsqs = sm + ((t & 1) ? SM_BSQ1 : SM_BSQ0);

        uint32_t bq[4];
#pragma unroll
        for (int j = 0; j < 4; j++)
            bq[j] = *reinterpret_cast<const uint32_t*>(
                bsqs + (wn * 32 + (j >> 1) * 16 + (j & 1) * 8 + (lane & 3) * 2) * 2);

        uint32_t acc[2][4][2];
#pragma unroll
        for (int ks = 0; ks < 4; ks++) {
            uint4 af[2], bf[2];
#pragma unroll
            for (int mt = 0; mt < 2; mt++)
                af[mt] = Au[(ks * 8 + wm * 2 + mt) * 32 + lane];
#pragma unroll
            for (int q = 0; q < 2; q++)
                bf[q] = Bu[(ks * 8 + wn * 2 + q) * 32 + lane];
#pragma unroll
            for (int mt = 0; mt < 2; mt++)
#pragma unroll
                for (int q = 0; q < 2; q++) {
                    if (ks == 0) {
                        mma_h_init(acc[mt][2 * q],     af[mt].x, af[mt].y, af[mt].z, af[mt].w,
                                   bf[q].x, bf[q].z, bq[2 * q]);
                        mma_h_init(acc[mt][2 * q + 1], af[mt].x, af[mt].y, af[mt].z, af[mt].w,
                                   bf[q].y, bf[q].w, bq[2 * q + 1]);
                    } else {
                        mma_h_acc(acc[mt][2 * q],     af[mt].x, af[mt].y, af[mt].z, af[mt].w,
                                  bf[q].x, bf[q].z);
                        mma_h_acc(acc[mt][2 * q + 1], af[mt].x, af[mt].y, af[mt].z, af[mt].w,
                                  bf[q].y, bf[q].w);
                    }
                }
        }

        // fold tile minimum per (mt, row-half) slot across the 4 j-blocks
#pragma unroll
        for (int mt = 0; mt < 2; mt++)
#pragma unroll
            for (int rh = 0; rh < 2; rh++) {
                __half2 mn = __hmin2(*reinterpret_cast<__half2*>(&acc[mt][0][rh]),
                                     *reinterpret_cast<__half2*>(&acc[mt][1][rh]));
                mn = __hmin2(mn, *reinterpret_cast<__half2*>(&acc[mt][2][rh]));
                mn = __hmin2(mn, *reinterpret_cast<__half2*>(&acc[mt][3][rh]));
                float2 f = __half22float2(mn);
                const int s = mt * 2 + rh;
                if (f.x < pmin[2 * s + 0]) { pmin[2 * s + 0] = f.x; ptile[2 * s + 0] = t; }
                if (f.y < pmin[2 * s + 1]) { pmin[2 * s + 1] = f.y; ptile[2 * s + 1] = t; }
            }

        CP_WAIT0();
        __syncthreads();
    }

    // ---- per-row winner (group) across parity and the 4 lane-pairs ----
    float* redv = reinterpret_cast<float*>(sm + SM_REDV);
    int*   redm = reinterpret_cast<int*>(sm + SM_REDM);
#pragma unroll
    for (int s = 0; s < 4; s++) {
        float v0 = pmin[2 * s], v1 = pmin[2 * s + 1];
        int h = (v1 < v0) ? 1 : 0;
        float v = h ? v1 : v0;
        int meta = (ptile[s * 2 + h] << 5) | (wn << 3) | ((lane & 3) * 2 + h);
#pragma unroll
        for (int mk = 1; mk <= 2; mk <<= 1) {
            float ov = __shfl_xor_sync(0xffffffffu, v, mk);
            int om = __shfl_xor_sync(0xffffffffu, meta, mk);
            if (ov < v) { v = ov; meta = om; }
        }
        if ((lane & 3) == 0) {
            int row = wm * 32 + (s >> 1) * 16 + (s & 1) * 8 + (lane >> 2);
            redv[row * 4 + wn] = v;
            redm[row * 4 + wn] = meta;
        }
    }
    __syncthreads();

    // ---- exact fp32 recompute: 4 threads/row, 1 candidate column each ----
    float* ws = reinterpret_cast<float*>(sm + SM_WS);
    {
        const int row = tid >> 2, tp = tid & 3;
        float bv = redv[row * 4 + 0];
        int bm = redm[row * 4 + 0];
#pragma unroll
        for (int w = 1; w < 4; w++) {
            float v = redv[row * 4 + w];
            if (v < bv) { bv = v; bm = redm[row * 4 + w]; }
        }
        int col = (bm >> 5) * 128 + ((bm >> 3) & 3) * 32 + (bm & 7) + tp * 8;

        const float4* ar = reinterpret_cast<const float4*>(A) + (size_t)(rowbase + row) * 16;
        const float4* br = reinterpret_cast<const float4*>(B) + (size_t)col * 16;
        float s = 0.f;
#pragma unroll
        for (int i = 0; i < 16; i++) {
            float4 a4 = ar[i], b4 = br[i];
            float dx = a4.x - b4.x, dy = a4.y - b4.y;
            float dz = a4.z - b4.z, dw = a4.w - b4.w;
            s += dx * dx + dy * dy + dz * dz + dw * dw;
        }
        s = fminf(s, __shfl_xor_sync(0xffffffffu, s, 1));
        s = fminf(s, __shfl_xor_sync(0xffffffffu, s, 2));
        float contrib = ((lane & 3) == 0) ? s : 0.f;
#pragma unroll
        for (int mk = 16; mk; mk >>= 1) contrib += __shfl_xor_sync(0xffffffffu, contrib, mk);
        if (lane == 0) ws[wid] = contrib;
    }
    __syncthreads();
    if (tid == 0) {
        float t = 0.f;
#pragma unroll
        for (int i = 0; i < 16; i++) t += ws[i];
        g_bsum[blockIdx.x] = t;
    }

    // ---- fused final reduction: last CTA sums all 128 partials ----
    __shared__ int s_last;
    __threadfence();
    if (tid == 0) s_last = (atomicAdd(&g_done, 1) == NBLK - 1) ? 1 : 0;
    __syncthreads();
    if (s_last && tid < 32) {
        __threadfence();
        float v = __ldcg(&g_bsum[tid]) + __ldcg(&g_bsum[tid + 32]) +
                  __ldcg(&g_bsum[tid + 64]) + __ldcg(&g_bsum[tid + 96]);
#pragma unroll
        for (int mk = 16; mk; mk >>= 1) v += __shfl_xor_sync(0xffffffffu, v, mk);
        if (tid == 0) out[0] = v;
    }
}

extern "C" void kernel_launch(void* const* d_in, const int* in_sizes, int n_in,
                              void* d_out, int out_size) {
    const float* A = (const float*)d_in[0];
    const float* B = (const float*)d_in[1];
    float* out = (float*)d_out;

    cudaFuncSetAttribute(dist_kernel, cudaFuncAttributeMaxDynamicSharedMemorySize, SMEM_BYTES);

    prep_kernel<<<512, 256>>>(A, B);
    dist_kernel<<<NBLK, NT, SMEM_BYTES>>>(A, B, out);
}

// round 10
// speedup vs baseline: 1.1957x; 1.1914x over previous
#include <cuda_runtime.h>
#include <cuda_fp16.h>
#include <cstdint>

// SimpleDistanceLoss:
//   search: S[m][n] = bsq[n] - 2<a_m,b_n> via fp16 m16n8k16 mma.sync, fp16
//           accumulators. bsq folded into the C operand of the first k-step.
//           BN=256 stages: 8 warps in 2(m) x 4(n), warp tile 64x64 ->
//           8 LDS.128 per 32 MMAs (R9 showed small tiles starve the pipe).
//   tail:   exact fp32 recompute over the 8 candidate columns of each row's
//           winning group.

#define NPTS   16384
#define DDIM   64
#define NT256  64               // number of 256-col tiles
#define NBLK   128

__device__ uint4 g_aunits[NBLK * 1024];    // fragment-unit layout of -2*A (fp16)
__device__ uint4 g_bunits[NBLK * 1024];    // fragment-unit layout of B (fp16)
__device__ __align__(16) __half g_bsqh[NPTS];
__device__ float g_bsum[NBLK];

// ---- smem byte offsets ----
#define SM_A     0
#define SM_B0    16384                     // 32768 B (256 cols)
#define SM_B1    49152
#define SM_BSQ0  81920                     // 512 B (256 halfs)
#define SM_BSQ1  82432
#define SM_REDV  82944                     // float[128][4]
#define SM_REDM  84992                     // int[128][4]
#define SM_WS    87040                     // float[8]
#define SMEM_BYTES 87072

static __device__ __forceinline__ uint32_t smem_u32(const void* p) {
    uint32_t a;
    asm("{ .reg .u64 t; cvta.to.shared.u64 t, %1; cvt.u32.u64 %0, t; }" : "=r"(a) : "l"(p));
    return a;
}
#define CP16(sm, gp) \
    asm volatile("cp.async.cg.shared.global [%0], [%1], 16;" :: "r"(sm), "l"(gp))
#define CP_COMMIT() asm volatile("cp.async.commit_group;" ::: "memory")
#define CP_WAIT0()  asm volatile("cp.async.wait_group 0;" ::: "memory")

static __device__ __forceinline__ void mma_h_acc(uint32_t c[2], uint32_t a0, uint32_t a1,
                                                 uint32_t a2, uint32_t a3,
                                                 uint32_t b0, uint32_t b1) {
    asm("mma.sync.aligned.m16n8k16.row.col.f16.f16.f16.f16 "
        "{%0,%1},{%2,%3,%4,%5},{%6,%7},{%0,%1};"
        : "+r"(c[0]), "+r"(c[1])
        : "r"(a0), "r"(a1), "r"(a2), "r"(a3), "r"(b0), "r"(b1));
}
static __device__ __forceinline__ void mma_h_init(uint32_t c[2], uint32_t a0, uint32_t a1,
                                                  uint32_t a2, uint32_t a3,
                                                  uint32_t b0, uint32_t b1, uint32_t bq) {
    asm("mma.sync.aligned.m16n8k16.row.col.f16.f16.f16.f16 "
        "{%0,%1},{%2,%3,%4,%5},{%6,%7},{%8,%8};"
        : "=r"(c[0]), "=r"(c[1])
        : "r"(a0), "r"(a1), "r"(a2), "r"(a3), "r"(b0), "r"(b1), "r"(bq));
}

// ---------------------------------------------------------------------------
// Prep (grid 256): fp32 -> fp16 (A scaled by -2), repack into the m16n8k16
// fragment-unit layout, compute fp16 bsq. Block b<128: A tile b; else B tile.
// Unit (ks, blk, s): 8 halfs {X[x][k],X[x][k+1], X[x+8][k],X[x+8][k+1],
//   X[x][k+8],X[x][k+9], X[x+8][k+8],X[x+8][k+9]}, x = blk*16+(s>>2),
//   k = ks*16+(s&3)*2.
// ---------------------------------------------------------------------------
__global__ __launch_bounds__(256)
void prep_kernel(const float* __restrict__ A, const float* __restrict__ B) {
    __shared__ __half sh[128 * 64];
    __shared__ float nr[256];
    const int tid = threadIdx.x;
    const bool isB = blockIdx.x >= NBLK;
    const int tile = blockIdx.x & (NBLK - 1);
    const float sc = isB ? 1.0f : -2.0f;

    const float4* s4 = reinterpret_cast<const float4*>(isB ? B : A) + (size_t)tile * 128 * 16;
    const int row = tid & 127, hf = tid >> 7;
    float nrm = 0.f;
    half2* sh2 = reinterpret_cast<half2*>(sh);
#pragma unroll
    for (int i = 0; i < 8; i++) {
        float4 v = s4[row * 16 + hf * 8 + i];
        nrm += v.x * v.x + v.y * v.y + v.z * v.z + v.w * v.w;
        sh2[row * 32 + hf * 16 + i * 2 + 0] = __floats2half2_rn(sc * v.x, sc * v.y);
        sh2[row * 32 + hf * 16 + i * 2 + 1] = __floats2half2_rn(sc * v.z, sc * v.w);
    }
    nr[tid] = nrm;
    __syncthreads();
    if (isB && tid < 128) g_bsqh[tile * 128 + tid] = __float2half_rn(nr[tid] + nr[tid + 128]);

    uint4* dst = (isB ? g_bunits : g_aunits) + (size_t)tile * 1024;
#pragma unroll
    for (int i = 0; i < 4; i++) {
        int u = tid + i * 256;
        int ks = u >> 8, blk = (u >> 5) & 7, s = u & 31;
        int x = blk * 16 + (s >> 2), k = ks * 16 + (s & 3) * 2;
        const uint32_t* p0 = reinterpret_cast<const uint32_t*>(&sh[x * 64 + k]);
        const uint32_t* p1 = reinterpret_cast<const uint32_t*>(&sh[(x + 8) * 64 + k]);
        uint4 v;
        v.x = p0[0]; v.y = p1[0]; v.z = p0[4]; v.w = p1[4];
        dst[u] = v;
    }
}

// ---------------------------------------------------------------------------
// Main: 128 CTAs x 256 threads; 8 warps in 2(m) x 4(n); warp tile 64x64.
// ---------------------------------------------------------------------------
__global__ __launch_bounds__(256, 1)
void dist_kernel(const float* __restrict__ A, const float* __restrict__ B) {
    extern __shared__ char sm[];
    const uint32_t smb = smem_u32(sm);
    const int tid = threadIdx.x;
    const int wid = tid >> 5, lane = tid & 31;
    const int wm = wid & 1, wn = wid >> 1;     // rows wm*64, cols wn*64 (of 256)
    const int rowbase = blockIdx.x * 128;
    const int c128 = wn >> 1;                  // which 128-col unit group
    const int w4 = (wn & 1) * 4;               // block offset inside the group

    // ---- prologue: A units + B tile 0 (256 cols) + bsq ----
    {
        const uint4* gA = g_aunits + (size_t)blockIdx.x * 1024;
        const uint4* gB = g_bunits;
#pragma unroll
        for (int i = 0; i < 4; i++) {
            int u = tid + i * 256;
            CP16(smb + SM_A + u * 16, gA + u);
            CP16(smb + SM_B0 + u * 16, gB + u);
            CP16(smb + SM_B0 + 16384 + u * 16, gB + 1024 + u);
        }
        if (tid < 32) CP16(smb + SM_BSQ0 + tid * 16, reinterpret_cast<const uint4*>(g_bsqh) + tid);
        CP_COMMIT();
        CP_WAIT0();
        __syncthreads();
    }

    const uint4* Au = reinterpret_cast<const uint4*>(sm + SM_A);
    float pmin[16];
    int ptile[16];
#pragma unroll
    for (int s = 0; s < 16; s++) { pmin[s] = 3.4e38f; ptile[s] = 0; }

    for (int t = 0; t < NT256; t++) {
        if (t + 1 < NT256) {
            const uint4* gB = g_bunits + (size_t)(t + 1) * 2048;
            const uint32_t dstB = smb + ((t & 1) ? SM_B0 : SM_B1);
#pragma unroll
            for (int i = 0; i < 8; i++) {
                int u = tid + i * 256;
                CP16(dstB + u * 16, gB + u);
            }
            if (tid < 32)
                CP16(smb + ((t & 1) ? SM_BSQ0 : SM_BSQ1) + tid * 16,
                     reinterpret_cast<const uint4*>(g_bsqh + (t + 1) * 256) + tid);
            CP_COMMIT();
        }

        const uint4* Bu = reinterpret_cast<const uint4*>(sm + ((t & 1) ? SM_B1 : SM_B0)) +
                          c128 * 1024;
        const char* bsqs = sm + ((t & 1) ? SM_BSQ1 : SM_BSQ0);

        uint32_t bq[8];
#pragma unroll
        for (int j = 0; j < 8; j++)
            bq[j] = *reinterpret_cast<const uint32_t*>(
                bsqs + (wn * 64 + (j >> 1) * 16 + (j & 1) * 8 + (lane & 3) * 2) * 2);

        uint32_t acc[4][8][2];
#pragma unroll
        for (int ks = 0; ks < 4; ks++) {
            uint4 af[4], bf[4];
#pragma unroll
            for (int mt = 0; mt < 4; mt++)
                af[mt] = Au[(ks * 8 + wm * 4 + mt) * 32 + lane];
#pragma unroll
            for (int p = 0; p < 4; p++)
                bf[p] = Bu[(ks * 8 + w4 + p) * 32 + lane];
#pragma unroll
            for (int mt = 0; mt < 4; mt++)
#pragma unroll
                for (int p = 0; p < 4; p++) {
                    if (ks == 0) {
                        mma_h_init(acc[mt][2 * p],     af[mt].x, af[mt].y, af[mt].z, af[mt].w,
                                   bf[p].x, bf[p].z, bq[2 * p]);
                        mma_h_init(acc[mt][2 * p + 1], af[mt].x, af[mt].y, af[mt].z, af[mt].w,
                                   bf[p].y, bf[p].w, bq[2 * p + 1]);
                    } else {
                        mma_h_acc(acc[mt][2 * p],     af[mt].x, af[mt].y, af[mt].z, af[mt].w,
                                  bf[p].x, bf[p].z);
                        mma_h_acc(acc[mt][2 * p + 1], af[mt].x, af[mt].y, af[mt].z, af[mt].w,
                                  bf[p].y, bf[p].w);
                    }
                }
        }

        // fold tile minimum per (mt, row-half) slot across the 8 j-blocks
#pragma unroll
        for (int mt = 0; mt < 4; mt++)
#pragma unroll
            for (int rh = 0; rh < 2; rh++) {
                __half2 mn = *reinterpret_cast<__half2*>(&acc[mt][0][rh]);
#pragma unroll
                for (int j = 1; j < 8; j++)
                    mn = __hmin2(mn, *reinterpret_cast<__half2*>(&acc[mt][j][rh]));
                float2 f = __half22float2(mn);
                const int s = mt * 2 + rh;
                if (f.x < pmin[2 * s + 0]) { pmin[2 * s + 0] = f.x; ptile[2 * s + 0] = t; }
                if (f.y < pmin[2 * s + 1]) { pmin[2 * s + 1] = f.y; ptile[2 * s + 1] = t; }
            }

        CP_WAIT0();
        __syncthreads();
    }

    // ---- per-row winner (group) across parity and the 4 lane-pairs ----
    float* redv = reinterpret_cast<float*>(sm + SM_REDV);
    int*   redm = reinterpret_cast<int*>(sm + SM_REDM);
#pragma unroll
    for (int s = 0; s < 8; s++) {
        float v0 = pmin[2 * s], v1 = pmin[2 * s + 1];
        int h = (v1 < v0) ? 1 : 0;
        float v = h ? v1 : v0;
        int meta = (ptile[2 * s + h] << 5) | (wn << 3) | ((lane & 3) * 2 + h);
#pragma unroll
        for (int mk = 1; mk <= 2; mk <<= 1) {
            float ov = __shfl_xor_sync(0xffffffffu, v, mk);
            int om = __shfl_xor_sync(0xffffffffu, meta, mk);
            if (ov < v) { v = ov; meta = om; }
        }
        if ((lane & 3) == 0) {
            int row = wm * 64 + (s >> 1) * 16 + (s & 1) * 8 + (lane >> 2);
            redv[row * 4 + wn] = v;
            redm[row * 4 + wn] = meta;
        }
    }
    __syncthreads();

    // ---- exact fp32 recompute over the 8 candidate columns of the winner ----
    float* ws = reinterpret_cast<float*>(sm + SM_WS);
    if (tid < 128) {
        float bv = redv[tid * 4 + 0];
        int bm = redm[tid * 4 + 0];
#pragma unroll
        for (int w = 1; w < 4; w++) {
            float v = redv[tid * 4 + w];
            if (v < bv) { bv = v; bm = redm[tid * 4 + w]; }
        }
        int base = (bm >> 5) * 256 + ((bm >> 3) & 3) * 64 + (bm & 7);

        const float4* ar = reinterpret_cast<const float4*>(A) + (size_t)(rowbase + tid) * 16;
        float4 a4[16];
#pragma unroll
        for (int i = 0; i < 16; i++) a4[i] = ar[i];

        float best = 3.4e38f;
#pragma unroll
        for (int jj = 0; jj < 8; jj++) {
            int col = base + (jj >> 1) * 16 + (jj & 1) * 8;
            const float4* br = reinterpret_cast<const float4*>(B) + (size_t)col * 16;
            float s = 0.f;
#pragma unroll
            for (int i = 0; i < 16; i++) {
                float4 b4 = br[i];
                float dx = a4[i].x - b4.x, dy = a4[i].y - b4.y;
                float dz = a4[i].z - b4.z, dw = a4[i].w - b4.w;
                s += dx * dx + dy * dy + dz * dz + dw * dw;
            }
            best = fminf(best, s);
        }
#pragma unroll
        for (int mk = 16; mk; mk >>= 1) best += __shfl_xor_sync(0xffffffffu, best, mk);
        if (lane == 0) ws[wid] = best;
    }
    __syncthreads();
    if (tid == 0) {
        float t = 0.f;
#pragma unroll
        for (int i = 0; i < 4; i++) t += ws[i];
        g_bsum[blockIdx.x] = t;
    }
}

// ---------------------------------------------------------------------------
__global__ void final_reduce_kernel(float* __restrict__ out) {
    int lane = threadIdx.x;
    float v = 0.f;
#pragma unroll
    for (int i = 0; i < NBLK / 32; i++) v += g_bsum[lane + i * 32];
#pragma unroll
    for (int mk = 16; mk; mk >>= 1) v += __shfl_xor_sync(0xffffffffu, v, mk);
    if (lane == 0) out[0] = v;
}

extern "C" void kernel_launch(void* const* d_in, const int* in_sizes, int n_in,
                              void* d_out, int out_size) {
    const float* A = (const float*)d_in[0];
    const float* B = (const float*)d_in[1];
    float* out = (float*)d_out;

    cudaFuncSetAttribute(dist_kernel, cudaFuncAttributeMaxDynamicSharedMemorySize, SMEM_BYTES);

    prep_kernel<<<2 * NBLK, 256>>>(A, B);
    dist_kernel<<<NBLK, 256, SMEM_BYTES>>>(A, B);
    final_reduce_kernel<<<1, 32>>>(out);
}

// round 11
// speedup vs baseline: 1.2208x; 1.0210x over previous
#include <cuda_runtime.h>
#include <cuda_fp16.h>
#include <cstdint>

// SimpleDistanceLoss:
//   search: S[m][n] = bsq[n] - 2<a_m,b_n> via fp16 m16n8k16 mma.sync, fp16
//           accumulators. bsq folded into the C operand of the first k-step.
//           BN=256 stages; 8 warps in 2(m) x 4(n), warp tile 64x64.
//           A fragments preloaded into registers for the whole kernel
//           (tile-invariant) -> mainloop does only B-fragment LDS.
//   tail:   exact fp32 recompute over the 8 candidate columns of each row's
//           winning group.

#define NPTS   16384
#define DDIM   64
#define NT256  64               // number of 256-col tiles
#define NBLK   128

__device__ uint4 g_aunits[NBLK * 1024];    // fragment-unit layout of -2*A (fp16)
__device__ uint4 g_bunits[NBLK * 1024];    // fragment-unit layout of B (fp16)
__device__ __align__(16) __half g_bsqh[NPTS];
__device__ float g_bsum[NBLK];

// ---- smem byte offsets ----
#define SM_A     0
#define SM_B0    16384                     // 32768 B (256 cols)
#define SM_B1    49152
#define SM_BSQ0  81920                     // 512 B (256 halfs)
#define SM_BSQ1  82432
#define SM_REDV  82944                     // float[128][4]
#define SM_REDM  84992                     // int[128][4]
#define SM_WS    87040                     // float[8]
#define SMEM_BYTES 87072

static __device__ __forceinline__ uint32_t smem_u32(const void* p) {
    uint32_t a;
    asm("{ .reg .u64 t; cvta.to.shared.u64 t, %1; cvt.u32.u64 %0, t; }" : "=r"(a) : "l"(p));
    return a;
}
#define CP16(sm, gp) \
    asm volatile("cp.async.cg.shared.global [%0], [%1], 16;" :: "r"(sm), "l"(gp))
#define CP_COMMIT() asm volatile("cp.async.commit_group;" ::: "memory")
#define CP_WAIT0()  asm volatile("cp.async.wait_group 0;" ::: "memory")

static __device__ __forceinline__ void mma_h_acc(uint32_t c[2], uint32_t a0, uint32_t a1,
                                                 uint32_t a2, uint32_t a3,
                                                 uint32_t b0, uint32_t b1) {
    asm("mma.sync.aligned.m16n8k16.row.col.f16.f16.f16.f16 "
        "{%0,%1},{%2,%3,%4,%5},{%6,%7},{%0,%1};"
        : "+r"(c[0]), "+r"(c[1])
        : "r"(a0), "r"(a1), "r"(a2), "r"(a3), "r"(b0), "r"(b1));
}
static __device__ __forceinline__ void mma_h_init(uint32_t c[2], uint32_t a0, uint32_t a1,
                                                  uint32_t a2, uint32_t a3,
                                                  uint32_t b0, uint32_t b1, uint32_t bq) {
    asm("mma.sync.aligned.m16n8k16.row.col.f16.f16.f16.f16 "
        "{%0,%1},{%2,%3,%4,%5},{%6,%7},{%8,%8};"
        : "=r"(c[0]), "=r"(c[1])
        : "r"(a0), "r"(a1), "r"(a2), "r"(a3), "r"(b0), "r"(b1), "r"(bq));
}

// ---------------------------------------------------------------------------
// Prep (grid 256): fp32 -> fp16 (A scaled by -2), repack into the m16n8k16
// fragment-unit layout, compute fp16 bsq. Block b<128: A tile b; else B tile.
// Unit (ks, blk, s): 8 halfs {X[x][k],X[x][k+1], X[x+8][k],X[x+8][k+1],
//   X[x][k+8],X[x][k+9], X[x+8][k+8],X[x+8][k+9]}, x = blk*16+(s>>2),
//   k = ks*16+(s&3)*2.
// ---------------------------------------------------------------------------
__global__ __launch_bounds__(256)
void prep_kernel(const float* __restrict__ A, const float* __restrict__ B) {
    __shared__ __half sh[128 * 64];
    __shared__ float nr[256];
    const int tid = threadIdx.x;
    const bool isB = blockIdx.x >= NBLK;
    const int tile = blockIdx.x & (NBLK - 1);
    const float sc = isB ? 1.0f : -2.0f;

    const float4* s4 = reinterpret_cast<const float4*>(isB ? B : A) + (size_t)tile * 128 * 16;
    const int row = tid & 127, hf = tid >> 7;
    float nrm = 0.f;
    half2* sh2 = reinterpret_cast<half2*>(sh);
#pragma unroll
    for (int i = 0; i < 8; i++) {
        float4 v = s4[row * 16 + hf * 8 + i];
        nrm += v.x * v.x + v.y * v.y + v.z * v.z + v.w * v.w;
        sh2[row * 32 + hf * 16 + i * 2 + 0] = __floats2half2_rn(sc * v.x, sc * v.y);
        sh2[row * 32 + hf * 16 + i * 2 + 1] = __floats2half2_rn(sc * v.z, sc * v.w);
    }
    nr[tid] = nrm;
    __syncthreads();
    if (isB && tid < 128) g_bsqh[tile * 128 + tid] = __float2half_rn(nr[tid] + nr[tid + 128]);

    uint4* dst = (isB ? g_bunits : g_aunits) + (size_t)tile * 1024;
#pragma unroll
    for (int i = 0; i < 4; i++) {
        int u = tid + i * 256;
        int ks = u >> 8, blk = (u >> 5) & 7, s = u & 31;
        int x = blk * 16 + (s >> 2), k = ks * 16 + (s & 3) * 2;
        const uint32_t* p0 = reinterpret_cast<const uint32_t*>(&sh[x * 64 + k]);
        const uint32_t* p1 = reinterpret_cast<const uint32_t*>(&sh[(x + 8) * 64 + k]);
        uint4 v;
        v.x = p0[0]; v.y = p1[0]; v.z = p0[4]; v.w = p1[4];
        dst[u] = v;
    }
}

// ---------------------------------------------------------------------------
// Main: 128 CTAs x 256 threads; 8 warps in 2(m) x 4(n); warp tile 64x64.
// A fragments live in registers for the entire kernel.
// ---------------------------------------------------------------------------
__global__ __launch_bounds__(256, 1)
void dist_kernel(const float* __restrict__ A, const float* __restrict__ B) {
    extern __shared__ char sm[];
    const uint32_t smb = smem_u32(sm);
    const int tid = threadIdx.x;
    const int wid = tid >> 5, lane = tid & 31;
    const int wm = wid & 1, wn = wid >> 1;     // rows wm*64, cols wn*64 (of 256)
    const int rowbase = blockIdx.x * 128;
    const int c128 = wn >> 1;                  // which 128-col unit group
    const int w4 = (wn & 1) * 4;               // block offset inside the group

    // ---- prologue: A units + B tile 0 (256 cols) + bsq ----
    {
        const uint4* gA = g_aunits + (size_t)blockIdx.x * 1024;
        const uint4* gB = g_bunits;
#pragma unroll
        for (int i = 0; i < 4; i++) {
            int u = tid + i * 256;
            CP16(smb + SM_A + u * 16, gA + u);
            CP16(smb + SM_B0 + u * 16, gB + u);
            CP16(smb + SM_B0 + 16384 + u * 16, gB + 1024 + u);
        }
        if (tid < 32) CP16(smb + SM_BSQ0 + tid * 16, reinterpret_cast<const uint4*>(g_bsqh) + tid);
        CP_COMMIT();
        CP_WAIT0();
        __syncthreads();
    }

    // ---- preload A fragments into registers (tile-invariant) ----
    uint4 areg[4][4];
    {
        const uint4* Au = reinterpret_cast<const uint4*>(sm + SM_A);
#pragma unroll
        for (int ks = 0; ks < 4; ks++)
#pragma unroll
            for (int mt = 0; mt < 4; mt++)
                areg[ks][mt] = Au[(ks * 8 + wm * 4 + mt) * 32 + lane];
    }

    float pmin[16];
    int ptile[16];
#pragma unroll
    for (int s = 0; s < 16; s++) { pmin[s] = 3.4e38f; ptile[s] = 0; }

    for (int t = 0; t < NT256; t++) {
        if (t + 1 < NT256) {
            const uint4* gB = g_bunits + (size_t)(t + 1) * 2048;
            const uint32_t dstB = smb + ((t & 1) ? SM_B0 : SM_B1);
#pragma unroll
            for (int i = 0; i < 8; i++) {
                int u = tid + i * 256;
                CP16(dstB + u * 16, gB + u);
            }
            if (tid < 32)
                CP16(smb + ((t & 1) ? SM_BSQ0 : SM_BSQ1) + tid * 16,
                     reinterpret_cast<const uint4*>(g_bsqh + (t + 1) * 256) + tid);
            CP_COMMIT();
        }

        const uint4* Bu = reinterpret_cast<const uint4*>(sm + ((t & 1) ? SM_B1 : SM_B0)) +
                          c128 * 1024;
        const char* bsqs = sm + ((t & 1) ? SM_BSQ1 : SM_BSQ0);

        uint32_t bq[8];
#pragma unroll
        for (int j = 0; j < 8; j++)
            bq[j] = *reinterpret_cast<const uint32_t*>(
                bsqs + (wn * 64 + (j >> 1) * 16 + (j & 1) * 8 + (lane & 3) * 2) * 2);

        uint32_t acc[4][8][2];
#pragma unroll
        for (int ks = 0; ks < 4; ks++) {
            uint4 bf[4];
#pragma unroll
            for (int p = 0; p < 4; p++)
                bf[p] = Bu[(ks * 8 + w4 + p) * 32 + lane];
#pragma unroll
            for (int mt = 0; mt < 4; mt++)
#pragma unroll
                for (int p = 0; p < 4; p++) {
                    const uint4 af = areg[ks][mt];
                    if (ks == 0) {
                        mma_h_init(acc[mt][2 * p],     af.x, af.y, af.z, af.w,
                                   bf[p].x, bf[p].z, bq[2 * p]);
                        mma_h_init(acc[mt][2 * p + 1], af.x, af.y, af.z, af.w,
                                   bf[p].y, bf[p].w, bq[2 * p + 1]);
                    } else {
                        mma_h_acc(acc[mt][2 * p],     af.x, af.y, af.z, af.w,
                                  bf[p].x, bf[p].z);
                        mma_h_acc(acc[mt][2 * p + 1], af.x, af.y, af.z, af.w,
                                  bf[p].y, bf[p].w);
                    }
                }
        }

        // fold tile minimum per (mt, row-half) slot across the 8 j-blocks
#pragma unroll
        for (int mt = 0; mt < 4; mt++)
#pragma unroll
            for (int rh = 0; rh < 2; rh++) {
                __half2 mn = *reinterpret_cast<__half2*>(&acc[mt][0][rh]);
#pragma unroll
                for (int j = 1; j < 8; j++)
                    mn = __hmin2(mn, *reinterpret_cast<__half2*>(&acc[mt][j][rh]));
                float2 f = __half22float2(mn);
                const int s = mt * 2 + rh;
                if (f.x < pmin[2 * s + 0]) { pmin[2 * s + 0] = f.x; ptile[2 * s + 0] = t; }
                if (f.y < pmin[2 * s + 1]) { pmin[2 * s + 1] = f.y; ptile[2 * s + 1] = t; }
            }

        CP_WAIT0();
        __syncthreads();
    }

    // ---- per-row winner (group) across parity and the 4 lane-pairs ----
    float* redv = reinterpret_cast<float*>(sm + SM_REDV);
    int*   redm = reinterpret_cast<int*>(sm + SM_REDM);
#pragma unroll
    for (int s = 0; s < 8; s++) {
        float v0 = pmin[2 * s], v1 = pmin[2 * s + 1];
        int h = (v1 < v0) ? 1 : 0;
        float v = h ? v1 : v0;
        int meta = (ptile[2 * s + h] << 5) | (wn << 3) | ((lane & 3) * 2 + h);
#pragma unroll
        for (int mk = 1; mk <= 2; mk <<= 1) {
            float ov = __shfl_xor_sync(0xffffffffu, v, mk);
            int om = __shfl_xor_sync(0xffffffffu, meta, mk);
            if (ov < v) { v = ov; meta = om; }
        }
        if ((lane & 3) == 0) {
            int row = wm * 64 + (s >> 1) * 16 + (s & 1) * 8 + (lane >> 2);
            redv[row * 4 + wn] = v;
            redm[row * 4 + wn] = meta;
        }
    }
    __syncthreads();

    // ---- exact fp32 recompute over the 8 candidate columns of the winner ----
    float* ws = reinterpret_cast<float*>(sm + SM_WS);
    if (tid < 128) {
        float bv = redv[tid * 4 + 0];
        int bm = redm[tid * 4 + 0];
#pragma unroll
        for (int w = 1; w < 4; w++) {
            float v = redv[tid * 4 + w];
            if (v < bv) { bv = v; bm = redm[tid * 4 + w]; }
        }
        int base = (bm >> 5) * 256 + ((bm >> 3) & 3) * 64 + (bm & 7);

        const float4* ar = reinterpret_cast<const float4*>(A) + (size_t)(rowbase + tid) * 16;
        float4 a4[16];
#pragma unroll
        for (int i = 0; i < 16; i++) a4[i] = ar[i];

        float best = 3.4e38f;
#pragma unroll
        for (int jj = 0; jj < 8; jj++) {
            int col = base + (jj >> 1) * 16 + (jj & 1) * 8;
            const float4* br = reinterpret_cast<const float4*>(B) + (size_t)col * 16;
            float s = 0.f;
#pragma unroll
            for (int i = 0; i < 16; i++) {
                float4 b4 = br[i];
                float dx = a4[i].x - b4.x, dy = a4[i].y - b4.y;
                float dz = a4[i].z - b4.z, dw = a4[i].w - b4.w;
                s += dx * dx + dy * dy + dz * dz + dw * dw;
            }
            best = fminf(best, s);
        }
#pragma unroll
        for (int mk = 16; mk; mk >>= 1) best += __shfl_xor_sync(0xffffffffu, best, mk);
        if (lane == 0) ws[wid] = best;
    }
    __syncthreads();
    if (tid == 0) {
        float t = 0.f;
#pragma unroll
        for (int i = 0; i < 4; i++) t += ws[i];
        g_bsum[blockIdx.x] = t;
    }
}

// ---------------------------------------------------------------------------
__global__ void final_reduce_kernel(float* __restrict__ out) {
    int lane = threadIdx.x;
    float v = 0.f;
#pragma unroll
    for (int i = 0; i < NBLK / 32; i++) v += g_bsum[lane + i * 32];
#pragma unroll
    for (int mk = 16; mk; mk >>= 1) v += __shfl_xor_sync(0xffffffffu, v, mk);
    if (lane == 0) out[0] = v;
}

extern "C" void kernel_launch(void* const* d_in, const int* in_sizes, int n_in,
                              void* d_out, int out_size) {
    const float* A = (const float*)d_in[0];
    const float* B = (const float*)d_in[1];
    float* out = (float*)d_out;

    cudaFuncSetAttribute(dist_kernel, cudaFuncAttributeMaxDynamicSharedMemorySize, SMEM_BYTES);

    prep_kernel<<<2 * NBLK, 256>>>(A, B);
    dist_kernel<<<NBLK, 256, SMEM_BYTES>>>(A, B);
    final_reduce_kernel<<<1, 32>>>(out);
}